// round 3
// baseline (speedup 1.0000x reference)
#include <cuda_runtime.h>

// PytorchLUTFakeQuant: t = clip(x*64, -128, 127); nearest of 16 sorted
// INTEGER centers (tie -> lower index); out = center / 64.
//
// 511-entry shared LUT indexed by ceil(clip(x*128, -256, 254)) + 256.
// ceil-count identity: #{m_i < u} == #{m_i <= ceil(u)-1} for integer m_i
// (exact, reproduces argmin lower-index tie-break).
//
// This round: exact-divide grid (no predicates), 8 float4 per thread
// (front-batched LDG.128, MLP=8), 5-op index math.

static constexpr int NC = 16;
static constexpr int LUT_SIZE = 512;          // indices 0..510 used
static constexpr int BLOCK = 256;
static constexpr int V = 8;                   // 8 x float4 = 32 floats/thread

__global__ void __launch_bounds__(BLOCK)
lut_fakequant_kernel(const float4* __restrict__ x,
                     const float* __restrict__ centers,
                     float4* __restrict__ out) {
    __shared__ float lut[LUT_SIZE];

    // ---- Build LUT (amortized over 32 elems/thread) ----
    float cv[NC];
#pragma unroll
    for (int i = 0; i < NC; i++) cv[i] = __ldg(&centers[i]);
    float m[NC - 1];
#pragma unroll
    for (int i = 0; i < NC - 1; i++) m[i] = cv[i] + cv[i + 1];  // integer, exact

    // lut[k] = cv[ #{ m_i <= k-257 } ] / 64
#pragma unroll
    for (int e = 0; e < LUT_SIZE / BLOCK; e++) {
        int k = threadIdx.x + e * BLOCK;
        float idxval = (float)(k - 257);
        int count = 0;
#pragma unroll
        for (int i = 0; i < NC - 1; i++) count += (m[i] <= idxval);
        lut[k] = cv[count] * 0.015625f;       // 1/64, exact
    }
    __syncthreads();

    // ---- Main loop: exactly V float4 per thread, no bounds checks ----
    int base = blockIdx.x * (BLOCK * V) + threadIdx.x;

    float4 v[V];
#pragma unroll
    for (int k = 0; k < V; k++)
        v[k] = x[base + k * BLOCK];           // 8 front-batched LDG.128

#pragma unroll
    for (int k = 0; k < V; k++) {
        float4 r;
        // 5 ops/elem: FMUL, FMNMX, F2I.RU, IADD, IMAX, then LDS.
        // fminf first so F2I can't overflow positive; F2I saturates INT_MIN
        // for very negative u, IADD keeps it negative, max(.,0) clamps.
#define QUANT_ONE(IN, OUT)                                   \
        do {                                                 \
            float u = fminf((IN) * 128.0f, 254.0f);          \
            int ki = max(__float2int_ru(u) + 256, 0);        \
            (OUT) = lut[ki];                                 \
        } while (0)
        QUANT_ONE(v[k].x, r.x);
        QUANT_ONE(v[k].y, r.y);
        QUANT_ONE(v[k].z, r.z);
        QUANT_ONE(v[k].w, r.w);
#undef QUANT_ONE
        out[base + k * BLOCK] = r;
    }
}

// Generic tail kernel (not used for this shape, kept for safety).
__global__ void lut_fakequant_tail(const float4* __restrict__ x,
                                   const float* __restrict__ centers,
                                   float4* __restrict__ out,
                                   int start4, int n4) {
    __shared__ float lut[LUT_SIZE];
    if (threadIdx.x < LUT_SIZE) {
        int k = threadIdx.x;
        float idxval = (float)(k - 257);
        int count = 0;
        for (int i = 0; i < NC - 1; i++)
            count += (__ldg(&centers[i]) + __ldg(&centers[i + 1]) <= idxval);
        lut[k] = __ldg(&centers[count]) * 0.015625f;
    }
    __syncthreads();
    int i = start4 + blockIdx.x * blockDim.x + threadIdx.x;
    if (i >= n4) return;
    float4 v = x[i], r;
#define QUANT_ONE(IN, OUT)                                   \
    do {                                                     \
        float u = fminf((IN) * 128.0f, 254.0f);              \
        int ki = max(__float2int_ru(u) + 256, 0);            \
        (OUT) = lut[ki];                                     \
    } while (0)
    QUANT_ONE(v.x, r.x); QUANT_ONE(v.y, r.y);
    QUANT_ONE(v.z, r.z); QUANT_ONE(v.w, r.w);
#undef QUANT_ONE
    out[i] = r;
}

extern "C" void kernel_launch(void* const* d_in, const int* in_sizes, int n_in,
                              void* d_out, int out_size) {
    const float* x = (const float*)d_in[0];
    const float* centers = (const float*)d_in[1];
    if (n_in >= 2 && in_sizes[0] == NC && in_sizes[1] != NC) {
        x = (const float*)d_in[1];
        centers = (const float*)d_in[0];
    }

    int n4 = out_size / 4;                    // 3,211,264
    int per_block = BLOCK * V;                // 2048 float4
    int main_blocks = n4 / per_block;         // 1568 exact for this shape

    if (main_blocks > 0)
        lut_fakequant_kernel<<<main_blocks, BLOCK>>>(
            (const float4*)x, centers, (float4*)d_out);

    int done4 = main_blocks * per_block;
    int rem4 = n4 - done4;
    if (rem4 > 0)
        lut_fakequant_tail<<<(rem4 + 511) / 512, 512>>>(
            (const float4*)x, centers, (float4*)d_out, done4, n4);
}

// round 4
// speedup vs baseline: 1.0017x; 1.0017x over previous
#include <cuda_runtime.h>

// PytorchLUTFakeQuant: t = clip(x*64, -128, 127); nearest of 16 sorted
// INTEGER centers (tie -> lower index); out = center / 64.
//
// 511-entry shared LUT indexed by ceil(clip(x*128, -256, 254)) + 256.
// ceil-count identity: #{m_i < u} == #{m_i <= ceil(u)-1} for integer m_i
// (exact, reproduces argmin lower-index tie-break). Verified rel_err=0.
//
// Round 4: occupancy push. BLOCK=128, V=8, launch_bounds(128,12) caps regs
// at 42 -> 48 warps/SM. Index chain shortened to FMUL+2xFMNMX+F2I; the +256
// folds into the LDS immediate offset.

static constexpr int NC = 16;
static constexpr int LUT_SIZE = 512;          // indices 0..510 used
static constexpr int BLOCK = 128;
static constexpr int V = 8;                   // 8 x float4 = 32 floats/thread

__global__ void __launch_bounds__(BLOCK, 12)
lut_fakequant_kernel(const float4* __restrict__ x,
                     const float* __restrict__ centers,
                     float4* __restrict__ out) {
    __shared__ float lut[LUT_SIZE];

    // ---- Build LUT: lut[k] = cv[ #{ m_i <= k-257 } ] / 64 ----
    float cv[NC];
#pragma unroll
    for (int i = 0; i < NC; i++) cv[i] = __ldg(&centers[i]);
    float m[NC - 1];
#pragma unroll
    for (int i = 0; i < NC - 1; i++) m[i] = cv[i] + cv[i + 1];  // integer, exact

#pragma unroll
    for (int e = 0; e < LUT_SIZE / BLOCK; e++) {
        int k = threadIdx.x + e * BLOCK;
        float idxval = (float)(k - 257);
        int count = 0;
#pragma unroll
        for (int i = 0; i < NC - 1; i++) count += (m[i] <= idxval);
        lut[k] = cv[count] * 0.015625f;       // 1/64, exact
    }
    __syncthreads();

    // ---- Main: exactly V float4 per thread, no bounds checks ----
    int base = blockIdx.x * (BLOCK * V) + threadIdx.x;

    float4 v[V];
#pragma unroll
    for (int k = 0; k < V; k++)
        v[k] = x[base + k * BLOCK];           // 8 front-batched LDG.128

    const float* lutc = lut + 256;            // +256 folds into LDS imm offset

#pragma unroll
    for (int k = 0; k < V; k++) {
        float4 r;
        // FMUL, FMNMX, FMNMX, F2I.RU, LDS (imm offset). Clamp to [-256,254]:
        // spec clips t at -128 -> u >= -256 -> index 0 is the correct floor.
#define QUANT_ONE(IN, OUT)                                              \
        do {                                                            \
            float u = fminf(fmaxf((IN) * 128.0f, -256.0f), 254.0f);     \
            (OUT) = lutc[__float2int_ru(u)];                            \
        } while (0)
        QUANT_ONE(v[k].x, r.x);
        QUANT_ONE(v[k].y, r.y);
        QUANT_ONE(v[k].z, r.z);
        QUANT_ONE(v[k].w, r.w);
#undef QUANT_ONE
        out[base + k * BLOCK] = r;
    }
}

// Generic tail kernel (unused for this shape; kept for safety).
__global__ void lut_fakequant_tail(const float4* __restrict__ x,
                                   const float* __restrict__ centers,
                                   float4* __restrict__ out,
                                   int start4, int n4) {
    __shared__ float lut[LUT_SIZE];
    if (threadIdx.x < LUT_SIZE) {
        int k = threadIdx.x;
        float idxval = (float)(k - 257);
        int count = 0;
        for (int i = 0; i < NC - 1; i++)
            count += (__ldg(&centers[i]) + __ldg(&centers[i + 1]) <= idxval);
        lut[k] = __ldg(&centers[count]) * 0.015625f;
    }
    __syncthreads();
    int i = start4 + blockIdx.x * blockDim.x + threadIdx.x;
    if (i >= n4) return;
    const float* lutc = lut + 256;
    float4 v = x[i], r;
#define QUANT_ONE(IN, OUT)                                              \
    do {                                                                \
        float u = fminf(fmaxf((IN) * 128.0f, -256.0f), 254.0f);         \
        (OUT) = lutc[__float2int_ru(u)];                                \
    } while (0)
    QUANT_ONE(v.x, r.x); QUANT_ONE(v.y, r.y);
    QUANT_ONE(v.z, r.z); QUANT_ONE(v.w, r.w);
#undef QUANT_ONE
    out[i] = r;
}

extern "C" void kernel_launch(void* const* d_in, const int* in_sizes, int n_in,
                              void* d_out, int out_size) {
    const float* x = (const float*)d_in[0];
    const float* centers = (const float*)d_in[1];
    if (n_in >= 2 && in_sizes[0] == NC && in_sizes[1] != NC) {
        x = (const float*)d_in[1];
        centers = (const float*)d_in[0];
    }

    int n4 = out_size / 4;                    // 3,211,264
    int per_block = BLOCK * V;                // 1024 float4
    int main_blocks = n4 / per_block;         // 3136 exact for this shape

    if (main_blocks > 0)
        lut_fakequant_kernel<<<main_blocks, BLOCK>>>(
            (const float4*)x, centers, (float4*)d_out);

    int done4 = main_blocks * per_block;
    int rem4 = n4 - done4;
    if (rem4 > 0)
        lut_fakequant_tail<<<(rem4 + 511) / 512, 512>>>(
            (const float4*)x, centers, (float4*)d_out, done4, n4);
}